// round 6
// baseline (speedup 1.0000x reference)
#include <cuda_runtime.h>
#include <math.h>

// 256^3 grid, 1 byte/voxel thermometer code: level L = 7 - d2 (d2 in 0..6),
// byte = (1<<L)-1. atomicOr of thermometer codes == thermometer of max level.
#define GDIM    256
#define WORDS   (GDIM*GDIM*GDIM/4)   // 4,194,304 u32 words per grid
#define VQUADS  (WORDS/4)            // 1,048,576 uint4 per grid
#define RBLOCKS 2048
#define RTHREADS 256
#define QPT     2                    // quads per thread
#define APB     51                   // atoms per splat block (51*5 = 255 slices)

__device__ uint4 g_src[VQUADS];      // zero at load; re-zeroed by reduce each call
__device__ uint4 g_tgt[VQUADS];
__device__ float g_part[RBLOCKS];
__device__ unsigned int g_count;

// 5-byte row patterns (dz = -2..2 in bytes 0..4), indexed by s2 = d0^2 + d1^2.
__device__ __constant__ unsigned long long c_PAT[8] = {
    0x00000007'3F7F3F07ULL,  // s2=0
    0x00000003'1F3F1F03ULL,  // s2=1
    0x00000001'0F1F0F01ULL,  // s2=2
    0ULL,
    0x00000000'03070300ULL,  // s2=4
    0x00000000'01030100ULL,  // s2=5
    0ULL, 0ULL
};

// Block handles APB atoms; first APB threads compute packed voxel indices once,
// then 5 slice-threads per atom do the atomicOr rows (d0 = slice - 2).
__global__ void splat_kernel(const float* __restrict__ src,
                             const float* __restrict__ tgt,
                             const float* __restrict__ ox,
                             const float* __restrict__ oy,
                             const float* __restrict__ oz,
                             const float* __restrict__ vx,
                             int N)
{
    __shared__ unsigned long long spat[8];
    __shared__ unsigned packed[APB];

    if (threadIdx.x < 8) spat[threadIdx.x] = c_PAT[threadIdx.x];

    int abase = blockIdx.x * APB;
    if (threadIdx.x < APB) {
        int a = abase + threadIdx.x;
        unsigned p = 0x80000000u;                 // invalid sentinel
        if (a < 2 * N) {
            bool isSrc = (a < N);
            const float* c = isSrc ? src : tgt;
            int n = isSrc ? a : (a - N);
            float v = vx[0];
            // IEEE f32 divide so floor matches the reference bit-exactly.
            float fx = __fdiv_rn(c[n]         - ox[0], v);
            float fy = __fdiv_rn(c[N + n]     - oy[0], v);
            float fz = __fdiv_rn(c[2 * N + n] - oz[0], v);
            int i0 = (int)floorf(fx);
            int i1 = (int)floorf(fy);
            int i2 = (int)floorf(fz);
            if ((unsigned)i0 <= 255u && (unsigned)i1 <= 255u && (unsigned)i2 <= 255u)
                p = ((unsigned)i0 << 16) | ((unsigned)i1 << 8) | (unsigned)i2;
        }
        packed[threadIdx.x] = p;
    }
    __syncthreads();

    int s = threadIdx.x;
    if (s >= APB * 5) return;
    int la = s / 5;
    int d0 = s - la * 5 - 2;
    unsigned p = packed[la];
    if (p & 0x80000000u) return;

    int a = abase + la;
    bool isSrc = (a < N);
    unsigned long long* grid = (unsigned long long*)(isSrc ? g_src : g_tgt);

    int i0 = (int)(p >> 16);
    int i1 = (int)((p >> 8) & 255u);
    int i2 = (int)(p & 255u);

    int j0 = i0 + d0;
    if ((unsigned)j0 > 255u) return;
    int d02 = d0 * d0;

    // z-clip shared across this slice's rows
    int start = i2 - 2;
    unsigned rsh = 0;
    if (start < 0) { rsh = (unsigned)(-start) * 8u; start = 0; }
    unsigned long long msk = ~0ULL;
    int avail = 256 - start;
    if (avail < 5) msk = (1ULL << (avail * 8)) - 1ULL;
    unsigned shl   = (unsigned)(start & 7) * 8u;
    unsigned qoff  = (unsigned)(start >> 3);
    unsigned rbase = ((unsigned)(j0 * 256 + i1)) * 32u + qoff;

#pragma unroll
    for (int d1 = -2; d1 <= 2; d1++) {
        int s2 = d02 + d1 * d1;
        if (s2 >= 8) continue;
        int j1 = i1 + d1;
        if ((unsigned)j1 > 255u) continue;
        unsigned long long pat = (spat[s2] >> rsh) & msk;
        __uint128_t sv = (__uint128_t)pat << shl;
        unsigned long long lo = (unsigned long long)sv;
        unsigned long long hi = (unsigned long long)(sv >> 64);
        unsigned q = rbase + (unsigned)d1 * 32u;
        if (lo) atomicOr(&grid[q], lo);
        if (hi) atomicOr(&grid[q + 1], hi);
    }
}

// Reduce + zero + final sum (last-block-done).
// src^2: per halfword, key = b0+b1 = 2^L1+2^L2-2 is a perfect hash of the
// unordered level pair; g(L1)+g(L2) symmetric -> one LDS per 2 voxels.
// cross: per byte, key = thermo(Ls)+thermo(Lt); both-occupied keys even,
// single-sided odd (LUT=0) -> branchless vadd4 decode on the rare taken path.
__global__ void reduce_kernel(float* __restrict__ out)
{
    __shared__ float s2tab[256];
    __shared__ float ctab[256];
    __shared__ float wsum[RTHREADS / 32];
    __shared__ double wsumd[RTHREADS / 32];
    __shared__ bool  isLast;

    const float KK = (float)((3.14159265358979323846 / 3.5) * (3.14159265358979323846 / 3.5));

    for (int i = threadIdx.x; i < 256; i += blockDim.x) { s2tab[i] = 0.0f; ctab[i] = 0.0f; }
    __syncthreads();
    if (threadIdx.x < 64) {
        int a = threadIdx.x >> 3, b = threadIdx.x & 7;
        int idx = (1 << a) + (1 << b) - 2;          // thermo(a)+thermo(b)
        float g1 = a ? expf(-2.0f * KK * (float)(7 - a)) : 0.0f;
        float g2 = b ? expf(-2.0f * KK * (float)(7 - b)) : 0.0f;
        s2tab[idx] = g1 + g2;
        ctab[idx]  = (a && b) ? expf(-KK * (float)(14 - a - b)) : 0.0f;
    }
    __syncthreads();

    float a0 = 0.0f, a1 = 0.0f, a2 = 0.0f, a3 = 0.0f;
    const uint4 z4 = make_uint4(0u, 0u, 0u, 0u);
    int base = (blockIdx.x * blockDim.x + threadIdx.x) * QPT;

    uint4 s[QPT], tq[QPT];
#pragma unroll
    for (int k = 0; k < QPT; k++) s[k]  = __ldcg(&g_src[base + k]);
#pragma unroll
    for (int k = 0; k < QPT; k++) tq[k] = __ldcg(&g_tgt[base + k]);

#pragma unroll
    for (int k = 0; k < QPT; k++) {
        unsigned sw[4] = { s[k].x,  s[k].y,  s[k].z,  s[k].w  };
        unsigned tw[4] = { tq[k].x, tq[k].y, tq[k].z, tq[k].w };
        unsigned sAny = sw[0] | sw[1] | sw[2] | sw[3];
        unsigned tAny = tw[0] | tw[1] | tw[2] | tw[3];
        if (sAny) {
            unsigned kk[8];
#pragma unroll
            for (int l = 0; l < 4; l++) {
                kk[2 * l]     = __dp4a(sw[l], 0x00000101u, 0u);
                kk[2 * l + 1] = __dp4a(sw[l], 0x01010000u, 0u);
            }
            a0 += s2tab[kk[0]]; a1 += s2tab[kk[1]];
            a2 += s2tab[kk[2]]; a3 += s2tab[kk[3]];
            a0 += s2tab[kk[4]]; a1 += s2tab[kk[5]];
            a2 += s2tab[kk[6]]; a3 += s2tab[kk[7]];

            unsigned uAny = (sw[0] & tw[0]) | (sw[1] & tw[1]) |
                            (sw[2] & tw[2]) | (sw[3] & tw[3]);
            if (uAny) {
#pragma unroll
                for (int l = 0; l < 4; l++) {
                    unsigned kw = __vaddus4(sw[l], tw[l]);
                    a0 -= ctab[kw & 255u];
                    a1 -= ctab[(kw >> 8)  & 255u];
                    a2 -= ctab[(kw >> 16) & 255u];
                    a3 -= ctab[kw >> 24];
                }
            }
            __stcg(&g_src[base + k], z4);    // reset for next graph replay
        }
        if (tAny) __stcg(&g_tgt[base + k], z4);
    }

    float acc = (a0 + a1) + (a2 + a3);
#pragma unroll
    for (int off = 16; off > 0; off >>= 1)
        acc += __shfl_down_sync(0xFFFFFFFFu, acc, off);
    int warp = threadIdx.x >> 5;
    if ((threadIdx.x & 31) == 0) wsum[warp] = acc;
    __syncthreads();
    if (threadIdx.x == 0) {
        float b = 0.0f;
#pragma unroll
        for (int wdx = 0; wdx < RTHREADS / 32; wdx++) b += wsum[wdx];
        g_part[blockIdx.x] = b;
        __threadfence();
        unsigned vdone = atomicAdd(&g_count, 1u);
        isLast = (vdone == (unsigned)gridDim.x - 1u);
        if (isLast) g_count = 0u;     // reset for next replay
    }
    __syncthreads();

    if (isLast) {
        double a = 0.0;
        for (int i = threadIdx.x; i < RBLOCKS; i += blockDim.x)
            a += (double)g_part[i];
#pragma unroll
        for (int off = 16; off > 0; off >>= 1)
            a += __shfl_down_sync(0xFFFFFFFFu, a, off);
        if ((threadIdx.x & 31) == 0) wsumd[warp] = a;
        __syncthreads();
        if (threadIdx.x == 0) {
            double tot = 0.0;
#pragma unroll
            for (int wdx = 0; wdx < RTHREADS / 32; wdx++) tot += wsumd[wdx];
            out[0] = (float)tot;
        }
    }
}

extern "C" void kernel_launch(void* const* d_in, const int* in_sizes, int n_in,
                              void* d_out, int out_size)
{
    const float* src = (const float*)d_in[0];
    const float* tgt = (const float*)d_in[1];
    const float* ox  = (const float*)d_in[2];
    const float* oy  = (const float*)d_in[3];
    const float* oz  = (const float*)d_in[4];
    const float* vx  = (const float*)d_in[5];
    int N = in_sizes[0] / 3;

    int blocks = (2 * N + APB - 1) / APB;
    splat_kernel<<<blocks, 256>>>(src, tgt, ox, oy, oz, vx, N);
    reduce_kernel<<<RBLOCKS, RTHREADS>>>((float*)d_out);
}

// round 7
// speedup vs baseline: 1.0918x; 1.0918x over previous
#include <cuda_runtime.h>
#include <math.h>

// 256^3 grid, 1 byte/voxel thermometer code: level L = 7 - d2 (d2 in 0..6),
// byte = (1<<L)-1. atomicOr of thermometer codes == thermometer of max level.
#define GDIM    256
#define WORDS   (GDIM*GDIM*GDIM/4)   // 4,194,304 u32 words per grid
#define VQUADS  (WORDS/4)            // 1,048,576 uint4 per grid
#define RBLOCKS 512
#define RTHREADS 512
#define QPT     4                    // quads per thread: VQUADS/(RBLOCKS*RTHREADS)

__device__ uint4 g_src[VQUADS];      // zero at load; re-zeroed by reduce each call
__device__ uint4 g_tgt[VQUADS];
__device__ float g_part[RBLOCKS];
__device__ unsigned int g_count;

// 5-byte row patterns (dz = -2..2 in bytes 0..4), indexed by s2 = d0^2 + d1^2.
__device__ __constant__ unsigned long long c_PAT[8] = {
    0x00000007'3F7F3F07ULL,  // s2=0
    0x00000003'1F3F1F03ULL,  // s2=1
    0x00000001'0F1F0F01ULL,  // s2=2
    0ULL,
    0x00000000'03070300ULL,  // s2=4
    0x00000000'01030100ULL,  // s2=5
    0ULL, 0ULL
};

// One thread per (atom, d0 slice): 2N*5 threads total.  (R5 version — fastest.)
__global__ void splat_kernel(const float* __restrict__ src,
                             const float* __restrict__ tgt,
                             const float* __restrict__ ox,
                             const float* __restrict__ oy,
                             const float* __restrict__ oz,
                             const float* __restrict__ vx,
                             int N)
{
    __shared__ unsigned long long spat[8];
    if (threadIdx.x < 8) spat[threadIdx.x] = c_PAT[threadIdx.x];
    __syncthreads();

    int t = blockIdx.x * blockDim.x + threadIdx.x;
    if (t >= 2 * N * 5) return;
    int a  = t / 5;
    int d0 = t - a * 5 - 2;
    bool isSrc = (a < N);
    const float* c = isSrc ? src : tgt;
    unsigned long long* grid = (unsigned long long*)(isSrc ? g_src : g_tgt);
    int n = isSrc ? a : (a - N);

    float v = vx[0];
    // IEEE f32 divide so floor matches the reference bit-exactly.
    float fx = __fdiv_rn(c[n]         - ox[0], v);
    float fy = __fdiv_rn(c[N + n]     - oy[0], v);
    float fz = __fdiv_rn(c[2 * N + n] - oz[0], v);
    int i0 = (int)floorf(fx);
    int i1 = (int)floorf(fy);
    int i2 = (int)floorf(fz);
    if ((unsigned)i0 > 255u || (unsigned)i1 > 255u || (unsigned)i2 > 255u) return;

    int j0 = i0 + d0;
    if ((unsigned)j0 > 255u) return;
    int d02 = d0 * d0;

    // z-clip shared across this thread's rows
    int start = i2 - 2;
    unsigned rsh = 0;
    if (start < 0) { rsh = (unsigned)(-start) * 8u; start = 0; }
    unsigned long long msk = ~0ULL;
    int avail = 256 - start;
    if (avail < 5) msk = (1ULL << (avail * 8)) - 1ULL;
    unsigned shl   = (unsigned)(start & 7) * 8u;
    unsigned qoff  = (unsigned)(start >> 3);
    unsigned rbase = ((unsigned)(j0 * 256 + i1)) * 32u + qoff;

#pragma unroll
    for (int d1 = -2; d1 <= 2; d1++) {
        int s2 = d02 + d1 * d1;
        if (s2 >= 8) continue;
        int j1 = i1 + d1;
        if ((unsigned)j1 > 255u) continue;
        unsigned long long p = (spat[s2] >> rsh) & msk;
        __uint128_t sv = (__uint128_t)p << shl;
        unsigned long long lo = (unsigned long long)sv;
        unsigned long long hi = (unsigned long long)(sv >> 64);
        unsigned q = rbase + (unsigned)d1 * 32u;
        if (lo) atomicOr(&grid[q], lo);
        if (hi) atomicOr(&grid[q + 1], hi);
    }
}

// Reduce + zero + final sum (last-block-done).
// src^2: per halfword, key = b0+b1 = 2^L1+2^L2-2 is a perfect hash of the
// unordered level pair; g(L1)+g(L2) symmetric -> one LDS per 2 voxels.
// s2tab[0] = 0, so the lookup is branchless-safe on empty words.
// cross: per byte, key = thermo(Ls)+thermo(Lt); both-occupied keys even,
// single-sided odd (LUT=0) -> branchless vadd4 decode on the rare taken path.
__global__ void __launch_bounds__(RTHREADS) reduce_kernel(float* __restrict__ out)
{
    __shared__ float s2tab[256];
    __shared__ float ctab[256];
    __shared__ float wsum[RTHREADS / 32];
    __shared__ double wsumd[RTHREADS / 32];
    __shared__ bool  isLast;

    const float KK = (float)((3.14159265358979323846 / 3.5) * (3.14159265358979323846 / 3.5));

    for (int i = threadIdx.x; i < 256; i += blockDim.x) { s2tab[i] = 0.0f; ctab[i] = 0.0f; }
    __syncthreads();
    if (threadIdx.x < 64) {
        int a = threadIdx.x >> 3, b = threadIdx.x & 7;
        int idx = (1 << a) + (1 << b) - 2;          // thermo(a)+thermo(b)
        float g1 = a ? expf(-2.0f * KK * (float)(7 - a)) : 0.0f;
        float g2 = b ? expf(-2.0f * KK * (float)(7 - b)) : 0.0f;
        s2tab[idx] = g1 + g2;
        ctab[idx]  = (a && b) ? expf(-KK * (float)(14 - a - b)) : 0.0f;
    }
    __syncthreads();

    float a0 = 0.0f, a1 = 0.0f, a2 = 0.0f, a3 = 0.0f;
    const uint4 z4 = make_uint4(0u, 0u, 0u, 0u);
    int tbase = blockIdx.x * (RTHREADS * QPT) + threadIdx.x;

#pragma unroll
    for (int st = 0; st < QPT / 2; st++) {
        int i0 = tbase + (2 * st)     * RTHREADS;
        int i1 = tbase + (2 * st + 1) * RTHREADS;
        uint4 s0 = g_src[i0];
        uint4 s1 = g_src[i1];
        uint4 t0 = g_tgt[i0];
        uint4 t1 = g_tgt[i1];

        unsigned sw[8] = { s0.x, s0.y, s0.z, s0.w, s1.x, s1.y, s1.z, s1.w };
        unsigned tw[8] = { t0.x, t0.y, t0.z, t0.w, t1.x, t1.y, t1.z, t1.w };

        // branchless src^2 term (empty words hit s2tab[0] == 0)
#pragma unroll
        for (int l = 0; l < 8; l += 4) {
            unsigned k0 = __dp4a(sw[l],     0x00000101u, 0u);
            unsigned k1 = __dp4a(sw[l],     0x01010000u, 0u);
            unsigned k2 = __dp4a(sw[l + 1], 0x00000101u, 0u);
            unsigned k3 = __dp4a(sw[l + 1], 0x01010000u, 0u);
            unsigned k4 = __dp4a(sw[l + 2], 0x00000101u, 0u);
            unsigned k5 = __dp4a(sw[l + 2], 0x01010000u, 0u);
            unsigned k6 = __dp4a(sw[l + 3], 0x00000101u, 0u);
            unsigned k7 = __dp4a(sw[l + 3], 0x01010000u, 0u);
            a0 += s2tab[k0]; a1 += s2tab[k1];
            a2 += s2tab[k2]; a3 += s2tab[k3];
            a0 += s2tab[k4]; a1 += s2tab[k5];
            a2 += s2tab[k6]; a3 += s2tab[k7];
        }

        // cross term, rare
        unsigned uA = (sw[0] & tw[0]) | (sw[1] & tw[1]) | (sw[2] & tw[2]) | (sw[3] & tw[3]);
        unsigned uB = (sw[4] & tw[4]) | (sw[5] & tw[5]) | (sw[6] & tw[6]) | (sw[7] & tw[7]);
        if (uA | uB) {
#pragma unroll
            for (int l = 0; l < 8; l++) {
                unsigned kw = __vaddus4(sw[l], tw[l]);
                a0 -= ctab[kw & 255u];
                a1 -= ctab[(kw >> 8)  & 255u];
                a2 -= ctab[(kw >> 16) & 255u];
                a3 -= ctab[kw >> 24];
            }
        }

        // predicated zero-stores (reset for next graph replay)
        if (sw[0] | sw[1] | sw[2] | sw[3]) g_src[i0] = z4;
        if (sw[4] | sw[5] | sw[6] | sw[7]) g_src[i1] = z4;
        if (tw[0] | tw[1] | tw[2] | tw[3]) g_tgt[i0] = z4;
        if (tw[4] | tw[5] | tw[6] | tw[7]) g_tgt[i1] = z4;
    }

    float acc = (a0 + a1) + (a2 + a3);
#pragma unroll
    for (int off = 16; off > 0; off >>= 1)
        acc += __shfl_down_sync(0xFFFFFFFFu, acc, off);
    int warp = threadIdx.x >> 5;
    if ((threadIdx.x & 31) == 0) wsum[warp] = acc;
    __syncthreads();
    if (threadIdx.x == 0) {
        float b = 0.0f;
#pragma unroll
        for (int wdx = 0; wdx < RTHREADS / 32; wdx++) b += wsum[wdx];
        g_part[blockIdx.x] = b;
        __threadfence();
        unsigned vdone = atomicAdd(&g_count, 1u);
        isLast = (vdone == (unsigned)gridDim.x - 1u);
        if (isLast) g_count = 0u;     // reset for next replay
    }
    __syncthreads();

    if (isLast) {
        double a = (threadIdx.x < RBLOCKS) ? (double)g_part[threadIdx.x] : 0.0;
#pragma unroll
        for (int off = 16; off > 0; off >>= 1)
            a += __shfl_down_sync(0xFFFFFFFFu, a, off);
        if ((threadIdx.x & 31) == 0) wsumd[warp] = a;
        __syncthreads();
        if (threadIdx.x == 0) {
            double tot = 0.0;
#pragma unroll
            for (int wdx = 0; wdx < RTHREADS / 32; wdx++) tot += wsumd[wdx];
            out[0] = (float)tot;
        }
    }
}

extern "C" void kernel_launch(void* const* d_in, const int* in_sizes, int n_in,
                              void* d_out, int out_size)
{
    const float* src = (const float*)d_in[0];
    const float* tgt = (const float*)d_in[1];
    const float* ox  = (const float*)d_in[2];
    const float* oy  = (const float*)d_in[3];
    const float* oz  = (const float*)d_in[4];
    const float* vx  = (const float*)d_in[5];
    int N = in_sizes[0] / 3;

    int total = 2 * N * 5;
    int blocks = (total + 255) / 256;
    splat_kernel<<<blocks, 256>>>(src, tgt, ox, oy, oz, vx, N);
    reduce_kernel<<<RBLOCKS, RTHREADS>>>((float*)d_out);
}